// round 12
// baseline (speedup 1.0000x reference)
#include <cuda_runtime.h>
#include <cstdint>

#define NN   50000
#define DIN  96
#define DOUT 128
#define NE   800000
#define NB   49          // ceil(NN / 1024)

// Scratch (device-global: no allocations allowed)
__device__ __align__(16) float g_agg[NN * DIN];
__device__ int g_cnt[NN];
__device__ int g_rowstart[NN];   // block-local exclusive prefix
__device__ int g_cursor[NN];     // block-local cursor for fill
__device__ int g_bsum[NB];       // per-1024-block totals
__device__ int g_boff[NB];       // exclusive scan of g_bsum
__device__ int g_csr[NE];

// ---------------------------------------------------------------------------
// K1: zero counters
// ---------------------------------------------------------------------------
__global__ void zero_cnt_kernel() {
    int i = blockIdx.x * blockDim.x + threadIdx.x;
    if (i < NN) g_cnt[i] = 0;
}

// ---------------------------------------------------------------------------
// K2: in-degree counts, 4 edges/thread (int4) for atomic MLP
// ---------------------------------------------------------------------------
__global__ void count_kernel(const int* __restrict__ ei) {
    int t = blockIdx.x * blockDim.x + threadIdx.x;
    if (t < NE / 4) {
        int4 d = ((const int4*)(ei + NE))[t];
        atomicAdd(&g_cnt[d.x], 1);
        atomicAdd(&g_cnt[d.y], 1);
        atomicAdd(&g_cnt[d.z], 1);
        atomicAdd(&g_cnt[d.w], 1);
    }
}

// ---------------------------------------------------------------------------
// K3a: per-block (1024-wide) exclusive scan of counts; emit block totals
// ---------------------------------------------------------------------------
__global__ void __launch_bounds__(1024) scanA_kernel() {
    __shared__ int wsum[32];
    int tid = threadIdx.x, lane = tid & 31, wid = tid >> 5;
    int i = blockIdx.x * 1024 + tid;
    int v = (i < NN) ? g_cnt[i] : 0;
    int s = v;
    #pragma unroll
    for (int o = 1; o < 32; o <<= 1) {
        int t = __shfl_up_sync(0xffffffffu, s, o);
        if (lane >= o) s += t;
    }
    if (lane == 31) wsum[wid] = s;
    __syncthreads();
    if (wid == 0) {
        int ws = wsum[lane];
        #pragma unroll
        for (int o = 1; o < 32; o <<= 1) {
            int t = __shfl_up_sync(0xffffffffu, ws, o);
            if (lane >= o) ws += t;
        }
        wsum[lane] = ws;
    }
    __syncthreads();
    int excl = ((wid == 0) ? 0 : wsum[wid - 1]) + s - v;
    if (i < NN) { g_rowstart[i] = excl; g_cursor[i] = excl; }
    if (tid == 0) g_bsum[blockIdx.x] = wsum[31];
}

// ---------------------------------------------------------------------------
// K3b: exclusive scan of the 49 block totals (single warp, 2 elems/lane)
// ---------------------------------------------------------------------------
__global__ void scanB_kernel() {
    int lane = threadIdx.x;
    int v0 = (lane < NB) ? g_bsum[lane] : 0;
    int v1 = (lane + 32 < NB) ? g_bsum[lane + 32] : 0;
    int s0 = v0;
    #pragma unroll
    for (int o = 1; o < 32; o <<= 1) {
        int t = __shfl_up_sync(0xffffffffu, s0, o);
        if (lane >= o) s0 += t;
    }
    int tot0 = __shfl_sync(0xffffffffu, s0, 31);
    int s1 = v1;
    #pragma unroll
    for (int o = 1; o < 32; o <<= 1) {
        int t = __shfl_up_sync(0xffffffffu, s1, o);
        if (lane >= o) s1 += t;
    }
    if (lane < NB) g_boff[lane] = s0 - v0;
    if (lane + 32 < NB) g_boff[lane + 32] = tot0 + s1 - v1;
}

// ---------------------------------------------------------------------------
// K4: fill CSR, 4 edges/thread. Final slot = local cursor + block offset.
// ---------------------------------------------------------------------------
__global__ void fill_kernel(const int* __restrict__ ei) {
    int t = blockIdx.x * blockDim.x + threadIdx.x;
    if (t < NE / 4) {
        int4 s = ((const int4*)ei)[t];
        int4 d = ((const int4*)(ei + NE))[t];
        int p0 = atomicAdd(&g_cursor[d.x], 1);
        int p1 = atomicAdd(&g_cursor[d.y], 1);
        int p2 = atomicAdd(&g_cursor[d.z], 1);
        int p3 = atomicAdd(&g_cursor[d.w], 1);
        g_csr[p0 + g_boff[d.x >> 10]] = s.x;
        g_csr[p1 + g_boff[d.y >> 10]] = s.y;
        g_csr[p2 + g_boff[d.z >> 10]] = s.z;
        g_csr[p3 + g_boff[d.w >> 10]] = s.w;
    }
}

// ---------------------------------------------------------------------------
// K5: gather-mean. Warp per row, lanes 0..23 own one float4 each.
// Unrolled x8 over neighbors: 8 LDG.128 in flight per lane before any
// dependent FADD -> halves the exposed L2 round-trips vs x4.
// ---------------------------------------------------------------------------
__global__ void agg_kernel(const float* __restrict__ x) {
    int warp = (blockIdx.x * blockDim.x + threadIdx.x) >> 5;
    int lane = threadIdx.x & 31;
    if (warp >= NN || lane >= 24) return;
    int rs  = g_rowstart[warp] + g_boff[warp >> 10];
    int deg = g_cnt[warp];
    float4 a0 = make_float4(0.f, 0.f, 0.f, 0.f);
    float4 a1 = make_float4(0.f, 0.f, 0.f, 0.f);
    float4 a2 = make_float4(0.f, 0.f, 0.f, 0.f);
    float4 a3 = make_float4(0.f, 0.f, 0.f, 0.f);
    int j = 0;
    for (; j + 8 <= deg; j += 8) {
        int s[8];
        #pragma unroll
        for (int q = 0; q < 8; q++) s[q] = g_csr[rs + j + q];
        float4 v[8];
        #pragma unroll
        for (int q = 0; q < 8; q++)
            v[q] = ((const float4*)(x + (long)s[q] * DIN))[lane];
        a0.x += v[0].x; a0.y += v[0].y; a0.z += v[0].z; a0.w += v[0].w;
        a1.x += v[1].x; a1.y += v[1].y; a1.z += v[1].z; a1.w += v[1].w;
        a2.x += v[2].x; a2.y += v[2].y; a2.z += v[2].z; a2.w += v[2].w;
        a3.x += v[3].x; a3.y += v[3].y; a3.z += v[3].z; a3.w += v[3].w;
        a0.x += v[4].x; a0.y += v[4].y; a0.z += v[4].z; a0.w += v[4].w;
        a1.x += v[5].x; a1.y += v[5].y; a1.z += v[5].z; a1.w += v[5].w;
        a2.x += v[6].x; a2.y += v[6].y; a2.z += v[6].z; a2.w += v[6].w;
        a3.x += v[7].x; a3.y += v[7].y; a3.z += v[7].z; a3.w += v[7].w;
    }
    for (; j + 2 <= deg; j += 2) {
        int s0 = g_csr[rs + j];
        int s1 = g_csr[rs + j + 1];
        float4 v0 = ((const float4*)(x + (long)s0 * DIN))[lane];
        float4 v1 = ((const float4*)(x + (long)s1 * DIN))[lane];
        a0.x += v0.x; a0.y += v0.y; a0.z += v0.z; a0.w += v0.w;
        a1.x += v1.x; a1.y += v1.y; a1.z += v1.z; a1.w += v1.w;
    }
    if (j < deg) {
        int s0 = g_csr[rs + j];
        float4 v0 = ((const float4*)(x + (long)s0 * DIN))[lane];
        a0.x += v0.x; a0.y += v0.y; a0.z += v0.z; a0.w += v0.w;
    }
    float inv = 1.0f / (float)max(deg, 1);
    a0.x = (a0.x + a1.x + a2.x + a3.x) * inv;
    a0.y = (a0.y + a1.y + a2.y + a3.y) * inv;
    a0.z = (a0.z + a1.z + a2.z + a3.z) * inv;
    a0.w = (a0.w + a1.w + a2.w + a3.w) * inv;
    ((float4*)(g_agg + (long)warp * DIN))[lane] = a0;
}

// ---------------------------------------------------------------------------
// K6: out = relu( agg @ Wl^T + bl + x @ Wr^T )   (packed fp32x2 FFMA)
// 2 cols x 8 rows/thread, 32-row tiles, 64-col half per block, 3 CTAs/SM,
// register prefetch of next tile (measured neutral-to-equal, kept).
// ---------------------------------------------------------------------------
__device__ __forceinline__ unsigned long long ffma2_(unsigned long long a,
                                                     unsigned long long b,
                                                     unsigned long long c) {
    unsigned long long d;
    asm("fma.rn.f32x2 %0, %1, %2, %3;" : "=l"(d) : "l"(a), "l"(b), "l"(c));
    return d;
}

#define WPAD 100
#define SM_WL 0
#define SM_WR 6400
#define SM_X  12800
#define SM_A  15872
#define SM_FLOATS 18944   // 75776 bytes -> 3 CTAs/SM

__global__ void __launch_bounds__(128) gemm_kernel(
    const float* __restrict__ x, const float* __restrict__ Wl,
    const float* __restrict__ bl, const float* __restrict__ Wr,
    float* __restrict__ out) {
    extern __shared__ __align__(16) float sm[];
    float* sWl = sm + SM_WL;
    float* sWr = sm + SM_WR;
    float* sx  = sm + SM_X;
    float* sa  = sm + SM_A;

    int tid = threadIdx.x;
    int colbase = (blockIdx.x & 1) * 64;

    for (int i = tid; i < 64 * DIN; i += 128) {
        int c = i / DIN, k = i - c * DIN;
        sWl[c * WPAD + k] = Wl[(colbase + c) * DIN + k];
        sWr[c * WPAD + k] = Wr[(colbase + c) * DIN + k];
    }

    int ct = tid & 31;
    int rbase = (tid >> 5) * 8;
    int c0 = ct, c1 = ct + 32;
    float b0 = bl[colbase + c0];
    float b1 = bl[colbase + c1];

    // this thread's 6 staging slots (i = tid + j*128 over 768 float4/array)
    int srow[6], sq[6];
    #pragma unroll
    for (int j = 0; j < 6; j++) {
        int i = tid + j * 128;
        srow[j] = i / 24;
        sq[j] = i - srow[j] * 24;
    }

    const int NT = (NN + 31) / 32;  // 1563
    int stride = gridDim.x >> 1;
    int t = blockIdx.x >> 1;

    float4 rx[6], ra[6];
    if (t < NT) {
        #pragma unroll
        for (int j = 0; j < 6; j++) {
            int gr = t * 32 + srow[j]; if (gr >= NN) gr = NN - 1;
            rx[j] = ((const float4*)(x + (long)gr * DIN))[sq[j]];
            ra[j] = ((const float4*)(g_agg + (long)gr * DIN))[sq[j]];
        }
    }

    for (; t < NT; t += stride) {
        int row0 = t * 32;
        __syncthreads();   // prev tile compute done (weights staged on iter 0)
        #pragma unroll
        for (int j = 0; j < 6; j++) {
            ((float4*)(sx + srow[j] * DIN))[sq[j]] = rx[j];
            ((float4*)(sa + srow[j] * DIN))[sq[j]] = ra[j];
        }
        __syncthreads();

        // prefetch next tile into registers; LDG latency hidden by compute
        int tn = t + stride;
        if (tn < NT) {
            #pragma unroll
            for (int j = 0; j < 6; j++) {
                int gr = tn * 32 + srow[j]; if (gr >= NN) gr = NN - 1;
                rx[j] = ((const float4*)(x + (long)gr * DIN))[sq[j]];
                ra[j] = ((const float4*)(g_agg + (long)gr * DIN))[sq[j]];
            }
        }

        unsigned long long acc0[8], acc1[8];
        #pragma unroll
        for (int r = 0; r < 8; r++) { acc0[r] = 0ull; acc1[r] = 0ull; }

        #pragma unroll 4
        for (int k = 0; k < DIN; k += 4) {
            ulonglong2 wl0 = *(const ulonglong2*)(sWl + c0 * WPAD + k);
            ulonglong2 wl1 = *(const ulonglong2*)(sWl + c1 * WPAD + k);
            ulonglong2 wr0 = *(const ulonglong2*)(sWr + c0 * WPAD + k);
            ulonglong2 wr1 = *(const ulonglong2*)(sWr + c1 * WPAD + k);
            #pragma unroll
            for (int r = 0; r < 8; r++) {
                ulonglong2 av = *(const ulonglong2*)(sa + (rbase + r) * DIN + k);
                ulonglong2 xv = *(const ulonglong2*)(sx + (rbase + r) * DIN + k);
                acc0[r] = ffma2_(wl0.x, av.x, acc0[r]);
                acc0[r] = ffma2_(wl0.y, av.y, acc0[r]);
                acc0[r] = ffma2_(wr0.x, xv.x, acc0[r]);
                acc0[r] = ffma2_(wr0.y, xv.y, acc0[r]);
                acc1[r] = ffma2_(wl1.x, av.x, acc1[r]);
                acc1[r] = ffma2_(wl1.y, av.y, acc1[r]);
                acc1[r] = ffma2_(wr1.x, xv.x, acc1[r]);
                acc1[r] = ffma2_(wr1.y, xv.y, acc1[r]);
            }
        }

        #pragma unroll
        for (int r = 0; r < 8; r++) {
            int row = row0 + rbase + r;
            if (row < NN) {
                float l0 = __uint_as_float((unsigned)(acc0[r] & 0xffffffffull));
                float h0 = __uint_as_float((unsigned)(acc0[r] >> 32));
                float l1 = __uint_as_float((unsigned)(acc1[r] & 0xffffffffull));
                float h1 = __uint_as_float((unsigned)(acc1[r] >> 32));
                float v0 = l0 + h0 + b0;
                float v1 = l1 + h1 + b1;
                out[(long)row * DOUT + colbase + c0] = fmaxf(v0, 0.f);
                out[(long)row * DOUT + colbase + c1] = fmaxf(v1, 0.f);
            }
        }
    }
}

// ---------------------------------------------------------------------------
extern "C" void kernel_launch(void* const* d_in, const int* in_sizes, int n_in,
                              void* d_out, int out_size) {
    const float* x  = (const float*)d_in[0];
    const int*   ei = (const int*)d_in[1];
    const float* Wl = (const float*)d_in[2];
    const float* bl = (const float*)d_in[3];
    const float* Wr = (const float*)d_in[4];
    float* out = (float*)d_out;

    cudaFuncSetAttribute(gemm_kernel, cudaFuncAttributeMaxDynamicSharedMemorySize,
                         SM_FLOATS * (int)sizeof(float));

    zero_cnt_kernel<<<(NN + 255) / 256, 256>>>();
    count_kernel<<<(NE / 4 + 255) / 256, 256>>>(ei);
    scanA_kernel<<<NB, 1024>>>();
    scanB_kernel<<<1, 32>>>();
    fill_kernel<<<(NE / 4 + 255) / 256, 256>>>(ei);
    agg_kernel<<<(NN * 32 + 255) / 256, 256>>>(x);
    gemm_kernel<<<444, 128, SM_FLOATS * sizeof(float)>>>(x, Wl, bl, Wr, out);
}